// round 1
// baseline (speedup 1.0000x reference)
#include <cuda_runtime.h>
#include <cuda_bf16.h>
#include <math.h>

// Problem constants
#define TOK 50176            // 16 * 56 * 56 tokens
#define CDIM 384

// ---------------- scratch (device globals; no allocation allowed) ----------
__device__ float g_xn [TOK * 384];    // LN output
__device__ float g_qkv[TOK * 1152];   // QKV activations
__device__ float g_o  [TOK * 384];    // attention output (token order)
__device__ float g_h1 [TOK * 1536];   // MLP hidden

// ---------------- copy input -> residual stream (d_out) --------------------
__global__ void copy_kernel(const float4* __restrict__ src, float4* __restrict__ dst, int n4)
{
    int i = blockIdx.x * blockDim.x + threadIdx.x;
    if (i < n4) dst[i] = src[i];
}

// ---------------- LayerNorm (C=384), 128 threads per token -----------------
__global__ __launch_bounds__(128)
void ln_kernel(const float* __restrict__ x, const float* __restrict__ gw,
               const float* __restrict__ bw, float* __restrict__ out)
{
    __shared__ float rs[4], rq[4];
    int t = threadIdx.x;
    size_t base = (size_t)blockIdx.x * 384;
    float v0 = x[base + t], v1 = x[base + t + 128], v2 = x[base + t + 256];
    float s = v0 + v1 + v2;
    float q = v0*v0 + v1*v1 + v2*v2;
#pragma unroll
    for (int o = 16; o > 0; o >>= 1) {
        s += __shfl_xor_sync(0xffffffffu, s, o);
        q += __shfl_xor_sync(0xffffffffu, q, o);
    }
    if ((t & 31) == 0) { rs[t >> 5] = s; rq[t >> 5] = q; }
    __syncthreads();
    float mean = (rs[0] + rs[1] + rs[2] + rs[3]) * (1.0f / 384.0f);
    float var  = (rq[0] + rq[1] + rq[2] + rq[3]) * (1.0f / 384.0f) - mean * mean;
    float inv  = rsqrtf(var + 1e-5f);
    out[base + t]       = (v0 - mean) * inv * gw[t]       + bw[t];
    out[base + t + 128] = (v1 - mean) * inv * gw[t + 128] + bw[t + 128];
    out[base + t + 256] = (v2 - mean) * inv * gw[t + 256] + bw[t + 256];
}

// ---------------- tf32 tensor-core GEMM ------------------------------------
// C[M,N] = A[M,K] @ B[K,N] + bias  (+ epilogue)
// MODE 0: store C                MODE 1: store gelu(C)      MODE 2: Cout += C (residual)
#define BM 128
#define BN 128
#define BK 32

__device__ __forceinline__ unsigned f2tf(float f)
{
    unsigned r;
    asm("cvt.rna.tf32.f32 %0, %1;" : "=r"(r) : "f"(f));
    return r;
}

template<int MODE>
__global__ __launch_bounds__(256, 2)
void gemm_tf32(const float* __restrict__ A, const float* __restrict__ B,
               const float* __restrict__ bias, float* __restrict__ Cout,
               int M, int N, int K)
{
    __shared__ float As[BM][BK + 4];   // 128 x 36 floats (conflict-free frag loads)
    __shared__ float Bs[BK][BN + 4];   // 32 x 132 floats

    int tid  = threadIdx.x;
    int bm   = blockIdx.y, bn = blockIdx.x;
    int warp = tid >> 5, lane = tid & 31;
    int wm   = warp & 3;          // 4 warps along M (32 rows each)
    int wn   = warp >> 2;         // 2 warps along N (64 cols each)
    int g    = lane >> 2;         // groupID
    int t    = lane & 3;          // threadID_in_group

    float acc[2][8][4];
#pragma unroll
    for (int i = 0; i < 2; i++)
#pragma unroll
        for (int j = 0; j < 8; j++)
#pragma unroll
            for (int k = 0; k < 4; k++) acc[i][j][k] = 0.f;

    const float* Ab = A + (size_t)bm * BM * K;
    const float* Bb = B + bn * BN;

    for (int k0 = 0; k0 < K; k0 += BK) {
        // load A tile 128x32 (4 float4 per thread), convert to tf32 bits
#pragma unroll
        for (int p = 0; p < 4; p++) {
            int idx = tid + p * 256;
            int row = idx >> 3, c = idx & 7;
            float4 v = *(const float4*)(Ab + (size_t)row * K + k0 + c * 4);
            float* s = &As[row][c * 4];
            s[0] = __uint_as_float(f2tf(v.x));
            s[1] = __uint_as_float(f2tf(v.y));
            s[2] = __uint_as_float(f2tf(v.z));
            s[3] = __uint_as_float(f2tf(v.w));
        }
        // load B tile 32x128
#pragma unroll
        for (int p = 0; p < 4; p++) {
            int idx = tid + p * 256;
            int row = idx >> 5, c = idx & 31;
            float4 v = *(const float4*)(Bb + (size_t)(k0 + row) * N + c * 4);
            float* s = &Bs[row][c * 4];
            s[0] = __uint_as_float(f2tf(v.x));
            s[1] = __uint_as_float(f2tf(v.y));
            s[2] = __uint_as_float(f2tf(v.z));
            s[3] = __uint_as_float(f2tf(v.w));
        }
        __syncthreads();

#pragma unroll
        for (int ks = 0; ks < BK; ks += 8) {
            unsigned a[2][4], b[8][2];
#pragma unroll
            for (int mt = 0; mt < 2; mt++) {
                int m0 = wm * 32 + mt * 16 + g;
                a[mt][0] = __float_as_uint(As[m0][ks + t]);
                a[mt][1] = __float_as_uint(As[m0 + 8][ks + t]);
                a[mt][2] = __float_as_uint(As[m0][ks + t + 4]);
                a[mt][3] = __float_as_uint(As[m0 + 8][ks + t + 4]);
            }
#pragma unroll
            for (int nt = 0; nt < 8; nt++) {
                int n0 = wn * 64 + nt * 8 + g;
                b[nt][0] = __float_as_uint(Bs[ks + t][n0]);
                b[nt][1] = __float_as_uint(Bs[ks + t + 4][n0]);
            }
#pragma unroll
            for (int mt = 0; mt < 2; mt++)
#pragma unroll
                for (int nt = 0; nt < 8; nt++) {
                    asm volatile(
                        "mma.sync.aligned.m16n8k8.row.col.f32.tf32.tf32.f32 "
                        "{%0,%1,%2,%3}, {%4,%5,%6,%7}, {%8,%9}, {%0,%1,%2,%3};\n"
                        : "+f"(acc[mt][nt][0]), "+f"(acc[mt][nt][1]),
                          "+f"(acc[mt][nt][2]), "+f"(acc[mt][nt][3])
                        : "r"(a[mt][0]), "r"(a[mt][1]), "r"(a[mt][2]), "r"(a[mt][3]),
                          "r"(b[nt][0]), "r"(b[nt][1]));
                }
        }
        __syncthreads();
    }

    // epilogue
#pragma unroll
    for (int mt = 0; mt < 2; mt++) {
#pragma unroll
        for (int nt = 0; nt < 8; nt++) {
            int row = bm * BM + wm * 32 + mt * 16 + g;
            int col = bn * BN + wn * 64 + nt * 8 + t * 2;
            float b0 = bias[col], b1 = bias[col + 1];
            float v00 = acc[mt][nt][0] + b0, v01 = acc[mt][nt][1] + b1;
            float v10 = acc[mt][nt][2] + b0, v11 = acc[mt][nt][3] + b1;
            if (MODE == 1) {
                v00 = 0.5f * v00 * (1.f + erff(v00 * 0.70710678118654752f));
                v01 = 0.5f * v01 * (1.f + erff(v01 * 0.70710678118654752f));
                v10 = 0.5f * v10 * (1.f + erff(v10 * 0.70710678118654752f));
                v11 = 0.5f * v11 * (1.f + erff(v11 * 0.70710678118654752f));
            }
            size_t i0 = (size_t)row * N + col;
            size_t i1 = (size_t)(row + 8) * N + col;
            if (MODE == 2) {
                v00 += Cout[i0]; v01 += Cout[i0 + 1];
                v10 += Cout[i1]; v11 += Cout[i1 + 1];
            }
            Cout[i0] = v00; Cout[i0 + 1] = v01;
            Cout[i1] = v10; Cout[i1 + 1] = v11;
        }
    }
}

// ---------------- windowed attention: one block per (window, head) ---------
// qkv layout per token row (1152): [s=0 q | s=1 k | s=2 v], each [head*32 + d]
__global__ __launch_bounds__(128)
void attn_kernel(const float* __restrict__ qkv, const float* __restrict__ rpb,
                 float* __restrict__ o, int shift)
{
    __shared__ float qs[49][33], ksh[49][33], vsh[49][33];
    __shared__ float sm[49 * 49];

    int head = blockIdx.x % 12;
    int win  = blockIdx.x / 12;
    int bimg = win >> 6;
    int wi   = (win >> 3) & 7;
    int wj   = win & 7;
    int tid  = threadIdx.x;

    // gather q,k,v for this window/head (shift handled by index roll)
    for (int idx = tid; idx < 49 * 32; idx += 128) {
        int p = idx >> 5, d = idx & 31;
        int r = p / 7, c = p - r * 7;
        int hh = wi * 7 + r + shift; if (hh >= 56) hh -= 56;
        int ww = wj * 7 + c + shift; if (ww >= 56) ww -= 56;
        size_t tok = (size_t)bimg * 3136 + hh * 56 + ww;
        const float* bp = qkv + tok * 1152 + head * 32 + d;
        qs[p][d]  = bp[0] * 0.17677669529663687f;   // * HD^-0.5
        ksh[p][d] = bp[384];
        vsh[p][d] = bp[768];
    }
    __syncthreads();

    // scores + relative position bias + shift mask
    for (int idx = tid; idx < 2401; idx += 128) {
        int p = idx / 49, j = idx - p * 49;
        float s = 0.f;
#pragma unroll
        for (int d = 0; d < 32; d++) s += qs[p][d] * ksh[j][d];
        int rp = p / 7, cp = p - rp * 7;
        int rj = j / 7, cj = j - rj * 7;
        s += rpb[((rp - rj + 6) * 13 + (cp - cj + 6)) * 12 + head];
        if (shift > 0) {
            int hp = wi * 7 + rp, wp = wj * 7 + cp;
            int hj = wi * 7 + rj, wq = wj * 7 + cj;
            int regp = (hp < 49 ? 0 : (hp < 53 ? 1 : 2)) * 3 + (wp < 49 ? 0 : (wp < 53 ? 1 : 2));
            int regj = (hj < 49 ? 0 : (hj < 53 ? 1 : 2)) * 3 + (wq < 49 ? 0 : (wq < 53 ? 1 : 2));
            if (regp != regj) s -= 100.f;
        }
        sm[idx] = s;
    }
    __syncthreads();

    // row softmax (one thread per query row)
    if (tid < 49) {
        float mx = -1e30f;
        for (int j = 0; j < 49; j++) mx = fmaxf(mx, sm[tid * 49 + j]);
        float sum = 0.f;
        for (int j = 0; j < 49; j++) {
            float e = __expf(sm[tid * 49 + j] - mx);
            sm[tid * 49 + j] = e;
            sum += e;
        }
        float inv = 1.f / sum;
        for (int j = 0; j < 49; j++) sm[tid * 49 + j] *= inv;
    }
    __syncthreads();

    // O = P @ V, scatter back to token order (roll inverse == same index)
    for (int idx = tid; idx < 49 * 32; idx += 128) {
        int p = idx >> 5, d = idx & 31;
        float s = 0.f;
#pragma unroll
        for (int j = 0; j < 49; j++) s += sm[p * 49 + j] * vsh[j][d];
        int r = p / 7, c = p - r * 7;
        int hh = wi * 7 + r + shift; if (hh >= 56) hh -= 56;
        int ww = wj * 7 + c + shift; if (ww >= 56) ww -= 56;
        size_t tok = (size_t)bimg * 3136 + hh * 56 + ww;
        o[tok * 384 + head * 32 + d] = s;
    }
}

// ---------------- launcher --------------------------------------------------
extern "C" void kernel_launch(void* const* d_in, const int* in_sizes, int n_in,
                              void* d_out, int out_size)
{
    const float* x     = (const float*)d_in[0];
    const float* n1g   = (const float*)d_in[1];
    const float* n1b   = (const float*)d_in[2];
    const float* qkvw  = (const float*)d_in[3];
    const float* qkvb  = (const float*)d_in[4];
    const float* rpb   = (const float*)d_in[5];
    const float* projw = (const float*)d_in[6];
    const float* projb = (const float*)d_in[7];
    const float* n2g   = (const float*)d_in[8];
    const float* n2b   = (const float*)d_in[9];
    const float* fc1w  = (const float*)d_in[10];
    const float* fc1b  = (const float*)d_in[11];
    const float* fc2w  = (const float*)d_in[12];
    const float* fc2b  = (const float*)d_in[13];
    float* out = (float*)d_out;

    float *p_xn, *p_qkv, *p_o, *p_h1;
    cudaGetSymbolAddress((void**)&p_xn,  g_xn);
    cudaGetSymbolAddress((void**)&p_qkv, g_qkv);
    cudaGetSymbolAddress((void**)&p_o,   g_o);
    cudaGetSymbolAddress((void**)&p_h1,  g_h1);

    int n4 = TOK * 384 / 4;
    copy_kernel<<<(n4 + 255) / 256, 256>>>((const float4*)x, (float4*)out, n4);

    for (int i = 0; i < 2; i++) {
        int shift = i ? 3 : 0;
        // LN1
        ln_kernel<<<TOK, 128>>>(out, n1g + i * 384, n1b + i * 384, p_xn);
        // QKV projection
        gemm_tf32<0><<<dim3(9, 392), 256>>>(p_xn, qkvw + (size_t)i * 384 * 1152,
                                            qkvb + i * 1152, p_qkv, TOK, 1152, 384);
        // windowed attention
        attn_kernel<<<12288, 128>>>(p_qkv, rpb + i * 169 * 12, p_o, shift);
        // output projection + residual into stream
        gemm_tf32<2><<<dim3(3, 392), 256>>>(p_o, projw + (size_t)i * 384 * 384,
                                            projb + i * 384, out, TOK, 384, 384);
        // LN2
        ln_kernel<<<TOK, 128>>>(out, n2g + i * 384, n2b + i * 384, p_xn);
        // MLP fc1 + GELU
        gemm_tf32<1><<<dim3(12, 392), 256>>>(p_xn, fc1w + (size_t)i * 384 * 1536,
                                             fc1b + i * 1536, p_h1, TOK, 1536, 384);
        // MLP fc2 + residual
        gemm_tf32<2><<<dim3(3, 392), 256>>>(p_h1, fc2w + (size_t)i * 1536 * 384,
                                            fc2b + i * 384, out, TOK, 384, 1536);
    }
}

// round 2
// speedup vs baseline: 1.1515x; 1.1515x over previous
#include <cuda_runtime.h>
#include <cuda_bf16.h>
#include <math.h>

// Problem constants
#define TOK 50176            // 16 * 56 * 56 tokens
#define CDIM 384

// ---------------- scratch (device globals; no allocation allowed) ----------
__device__ float g_xn [TOK * 384];    // LN output
__device__ float g_qkv[TOK * 1152];   // QKV activations
__device__ float g_o  [TOK * 384];    // attention output (token order)
__device__ float g_h1 [TOK * 1536];   // MLP hidden

// ---------------- copy input -> residual stream (d_out) --------------------
__global__ void copy_kernel(const float4* __restrict__ src, float4* __restrict__ dst, int n4)
{
    int i = blockIdx.x * blockDim.x + threadIdx.x;
    if (i < n4) dst[i] = src[i];
}

// ---------------- LayerNorm (C=384), 128 threads per token -----------------
__global__ __launch_bounds__(128)
void ln_kernel(const float* __restrict__ x, const float* __restrict__ gw,
               const float* __restrict__ bw, float* __restrict__ out)
{
    __shared__ float rs[4], rq[4];
    int t = threadIdx.x;
    size_t base = (size_t)blockIdx.x * 384;
    float v0 = x[base + t], v1 = x[base + t + 128], v2 = x[base + t + 256];
    float s = v0 + v1 + v2;
    float q = v0*v0 + v1*v1 + v2*v2;
#pragma unroll
    for (int o = 16; o > 0; o >>= 1) {
        s += __shfl_xor_sync(0xffffffffu, s, o);
        q += __shfl_xor_sync(0xffffffffu, q, o);
    }
    if ((t & 31) == 0) { rs[t >> 5] = s; rq[t >> 5] = q; }
    __syncthreads();
    float mean = (rs[0] + rs[1] + rs[2] + rs[3]) * (1.0f / 384.0f);
    float var  = (rq[0] + rq[1] + rq[2] + rq[3]) * (1.0f / 384.0f) - mean * mean;
    float inv  = rsqrtf(var + 1e-5f);
    out[base + t]       = (v0 - mean) * inv * gw[t]       + bw[t];
    out[base + t + 128] = (v1 - mean) * inv * gw[t + 128] + bw[t + 128];
    out[base + t + 256] = (v2 - mean) * inv * gw[t + 256] + bw[t + 256];
}

// ---------------- tf32 tensor-core GEMM, 2-stage cp.async pipeline ---------
// C[M,N] = A[M,K] @ B[K,N] + bias  (+ epilogue)
// MODE 0: store C       MODE 1: store gelu(C)       MODE 2: Cout += C
#define BM 128
#define BN 128
#define BK 32
#define ASZ (128 * 36)          // A stage size in floats (pad to 36 for 16B align)
#define BSZ (32 * 132)          // B stage size in floats
#define GEMM_SMEM ((2 * ASZ + 2 * BSZ) * 4)

__device__ __forceinline__ void cp16(float* smem, const float* gmem)
{
    unsigned s = (unsigned)__cvta_generic_to_shared(smem);
    asm volatile("cp.async.cg.shared.global [%0], [%1], 16;\n" :: "r"(s), "l"(gmem));
}

template<int MODE>
__global__ __launch_bounds__(256, 2)
void gemm_tf32(const float* __restrict__ A, const float* __restrict__ B,
               const float* __restrict__ bias, float* __restrict__ Cout,
               int M, int N, int K)
{
    extern __shared__ float sh[];
    // layout: As[2][128][36] then Bs[2][32][132]

    int tid  = threadIdx.x;
    int bm   = blockIdx.y, bn = blockIdx.x;
    int warp = tid >> 5, lane = tid & 31;
    int wm   = warp & 3;          // 4 warps along M
    int wn   = warp >> 2;         // 2 warps along N
    int g    = lane >> 2;
    int t    = lane & 3;

    float acc[2][8][4];
#pragma unroll
    for (int i = 0; i < 2; i++)
#pragma unroll
        for (int j = 0; j < 8; j++)
#pragma unroll
            for (int k = 0; k < 4; k++) acc[i][j][k] = 0.f;

    const float* Ab = A + (size_t)bm * BM * K;
    const float* Bb = B + bn * BN;

    int arow = tid >> 3, acol = (tid & 7) * 4;   // A: 128 rows x 8 float4
    int brow = tid >> 5, bcol = (tid & 31) * 4;  // B: 32 rows x 32 float4

    // prologue: load stage 0
    {
        float* sA = sh;
        float* sB = sh + 2 * ASZ;
#pragma unroll
        for (int p = 0; p < 4; p++)
            cp16(sA + (arow + p * 32) * 36 + acol, Ab + (size_t)(arow + p * 32) * K + acol);
#pragma unroll
        for (int p = 0; p < 4; p++)
            cp16(sB + (brow + p * 8) * 132 + bcol, Bb + (size_t)(brow + p * 8) * N + bcol);
        asm volatile("cp.async.commit_group;\n");
    }

    int KT = K / BK;
    for (int kt = 0; kt < KT; kt++) {
        int st = kt & 1;
        if (kt + 1 < KT) {
            int k0 = (kt + 1) * BK;
            float* sA = sh + (st ^ 1) * ASZ;
            float* sB = sh + 2 * ASZ + (st ^ 1) * BSZ;
#pragma unroll
            for (int p = 0; p < 4; p++)
                cp16(sA + (arow + p * 32) * 36 + acol, Ab + (size_t)(arow + p * 32) * K + k0 + acol);
#pragma unroll
            for (int p = 0; p < 4; p++)
                cp16(sB + (brow + p * 8) * 132 + bcol, Bb + (size_t)(k0 + brow + p * 8) * N + bcol);
            asm volatile("cp.async.commit_group;\n");
            asm volatile("cp.async.wait_group 1;\n");
        } else {
            asm volatile("cp.async.wait_group 0;\n");
        }
        __syncthreads();

        const float* sA = sh + st * ASZ;
        const float* sB = sh + 2 * ASZ + st * BSZ;
#pragma unroll
        for (int ks = 0; ks < BK; ks += 8) {
            unsigned a[2][4], b[8][2];
#pragma unroll
            for (int mt = 0; mt < 2; mt++) {
                int m0 = wm * 32 + mt * 16 + g;
                a[mt][0] = __float_as_uint(sA[m0 * 36 + ks + t]);
                a[mt][1] = __float_as_uint(sA[(m0 + 8) * 36 + ks + t]);
                a[mt][2] = __float_as_uint(sA[m0 * 36 + ks + t + 4]);
                a[mt][3] = __float_as_uint(sA[(m0 + 8) * 36 + ks + t + 4]);
            }
#pragma unroll
            for (int nt = 0; nt < 8; nt++) {
                int n0 = wn * 64 + nt * 8 + g;
                b[nt][0] = __float_as_uint(sB[(ks + t) * 132 + n0]);
                b[nt][1] = __float_as_uint(sB[(ks + t + 4) * 132 + n0]);
            }
#pragma unroll
            for (int mt = 0; mt < 2; mt++)
#pragma unroll
                for (int nt = 0; nt < 8; nt++) {
                    asm volatile(
                        "mma.sync.aligned.m16n8k8.row.col.f32.tf32.tf32.f32 "
                        "{%0,%1,%2,%3}, {%4,%5,%6,%7}, {%8,%9}, {%0,%1,%2,%3};\n"
                        : "+f"(acc[mt][nt][0]), "+f"(acc[mt][nt][1]),
                          "+f"(acc[mt][nt][2]), "+f"(acc[mt][nt][3])
                        : "r"(a[mt][0]), "r"(a[mt][1]), "r"(a[mt][2]), "r"(a[mt][3]),
                          "r"(b[nt][0]), "r"(b[nt][1]));
                }
        }
        __syncthreads();
    }

    // epilogue
#pragma unroll
    for (int mt = 0; mt < 2; mt++) {
#pragma unroll
        for (int nt = 0; nt < 8; nt++) {
            int row = bm * BM + wm * 32 + mt * 16 + g;
            int col = bn * BN + wn * 64 + nt * 8 + t * 2;
            float b0 = bias[col], b1 = bias[col + 1];
            float v00 = acc[mt][nt][0] + b0, v01 = acc[mt][nt][1] + b1;
            float v10 = acc[mt][nt][2] + b0, v11 = acc[mt][nt][3] + b1;
            if (MODE == 1) {
                v00 = 0.5f * v00 * (1.f + erff(v00 * 0.70710678118654752f));
                v01 = 0.5f * v01 * (1.f + erff(v01 * 0.70710678118654752f));
                v10 = 0.5f * v10 * (1.f + erff(v10 * 0.70710678118654752f));
                v11 = 0.5f * v11 * (1.f + erff(v11 * 0.70710678118654752f));
            }
            size_t i0 = (size_t)row * N + col;
            size_t i1 = (size_t)(row + 8) * N + col;
            if (MODE == 2) {
                v00 += Cout[i0]; v01 += Cout[i0 + 1];
                v10 += Cout[i1]; v11 += Cout[i1 + 1];
            }
            Cout[i0] = v00; Cout[i0 + 1] = v01;
            Cout[i1] = v10; Cout[i1 + 1] = v11;
        }
    }
}

// ---------------- windowed attention: one block per (window, head) ---------
// qkv layout per token row (1152): [s=0 q | s=1 k | s=2 v], each [head*32 + d]
__global__ __launch_bounds__(128)
void attn_kernel(const float* __restrict__ qkv, const float* __restrict__ rpb,
                 float* __restrict__ o, int shift)
{
    __shared__ float qs[56][33];     // rows 49..55 read as garbage, results discarded
    __shared__ float ks[64][33];     // rows 49..63 garbage, discarded
    __shared__ float vs[49][36];     // padded to 36 for float4 loads
    __shared__ float sm[49 * 49];
    __shared__ float rps[169];

    int head = blockIdx.x % 12;
    int win  = blockIdx.x / 12;
    int bimg = win >> 6;
    int wi   = (win >> 3) & 7;
    int wj   = win & 7;
    int tid  = threadIdx.x;

    // preload relative position bias slice for this head
    for (int idx = tid; idx < 169; idx += 128) rps[idx] = rpb[idx * 12 + head];

    // gather q,k,v for this window/head (shift handled by index roll)
    for (int idx = tid; idx < 49 * 32; idx += 128) {
        int p = idx >> 5, d = idx & 31;
        int r = p / 7, c = p - r * 7;
        int hh = wi * 7 + r + shift; if (hh >= 56) hh -= 56;
        int ww = wj * 7 + c + shift; if (ww >= 56) ww -= 56;
        size_t tok = (size_t)bimg * 3136 + hh * 56 + ww;
        const float* bp = qkv + tok * 1152 + head * 32 + d;
        qs[p][d] = bp[0] * 0.17677669529663687f;
        ks[p][d] = bp[384];
        vs[p][d] = bp[768];
    }
    __syncthreads();

    // ---- scores: each thread computes a 7(p) x 4(j) register tile ----
    {
        int p0 = tid >> 4;          // 0..7  -> p = p0 + 8a
        int j0 = tid & 15;          // 0..15 -> j = j0 + 16b
        float acc[7][4];
#pragma unroll
        for (int a = 0; a < 7; a++)
#pragma unroll
            for (int b = 0; b < 4; b++) acc[a][b] = 0.f;

#pragma unroll 4
        for (int d = 0; d < 32; d++) {
            float kv[4];
#pragma unroll
            for (int b = 0; b < 4; b++) kv[b] = ks[j0 + 16 * b][d];
#pragma unroll
            for (int a = 0; a < 7; a++) {
                float qv = qs[p0 + 8 * a][d];
#pragma unroll
                for (int b = 0; b < 4; b++) acc[a][b] += qv * kv[b];
            }
        }

        // bias + shift-mask + store valid entries
#pragma unroll
        for (int a = 0; a < 7; a++) {
            int p = p0 + 8 * a;
            if (p < 49) {
                int rp = p / 7, cp = p - rp * 7;
                int regp = 0;
                if (shift > 0) {
                    int hp = wi * 7 + rp, wp_ = wj * 7 + cp;
                    regp = (hp < 49 ? 0 : (hp < 53 ? 1 : 2)) * 3 +
                           (wp_ < 49 ? 0 : (wp_ < 53 ? 1 : 2));
                }
#pragma unroll
                for (int b = 0; b < 4; b++) {
                    int j = j0 + 16 * b;
                    if (j < 49) {
                        int rj = j / 7, cj = j - rj * 7;
                        float s = acc[a][b] + rps[(rp - rj + 6) * 13 + (cp - cj + 6)];
                        if (shift > 0) {
                            int hj = wi * 7 + rj, wq = wj * 7 + cj;
                            int regj = (hj < 49 ? 0 : (hj < 53 ? 1 : 2)) * 3 +
                                       (wq < 49 ? 0 : (wq < 53 ? 1 : 2));
                            if (regp != regj) s -= 100.f;
                        }
                        sm[p * 49 + j] = s;
                    }
                }
            }
        }
    }
    __syncthreads();

    // ---- softmax: warp per row-set, lanes over columns ----
    {
        int wid = tid >> 5, lane = tid & 31;
        for (int r = wid; r < 49; r += 4) {
            float v0 = sm[r * 49 + lane];
            float v1 = (lane + 32 < 49) ? sm[r * 49 + lane + 32] : -1e30f;
            float mx = fmaxf(v0, v1);
#pragma unroll
            for (int off = 16; off > 0; off >>= 1)
                mx = fmaxf(mx, __shfl_xor_sync(0xffffffffu, mx, off));
            float e0 = __expf(v0 - mx);
            float e1 = (lane + 32 < 49) ? __expf(v1 - mx) : 0.f;
            float sum = e0 + e1;
#pragma unroll
            for (int off = 16; off > 0; off >>= 1)
                sum += __shfl_xor_sync(0xffffffffu, sum, off);
            float inv = 1.f / sum;
            sm[r * 49 + lane] = e0 * inv;
            if (lane + 32 < 49) sm[r * 49 + lane + 32] = e1 * inv;
        }
    }
    __syncthreads();

    // ---- O = P @ V: each thread 4(p) x 4(d) tile, float4 V loads ----
    {
        int pg = tid >> 3;           // 0..15 -> p = pg + 16a
        int d4 = (tid & 7) * 4;      // d base
        float oa[4][4];
#pragma unroll
        for (int a = 0; a < 4; a++)
#pragma unroll
            for (int k = 0; k < 4; k++) oa[a][k] = 0.f;

        for (int j = 0; j < 49; j++) {
            float4 vv = *(const float4*)&vs[j][d4];
#pragma unroll
            for (int a = 0; a < 4; a++) {
                int p = pg + 16 * a;
                int pr = p < 49 ? p : 0;         // clamp to stay in-bounds; discarded later
                float s = sm[pr * 49 + j];
                oa[a][0] += s * vv.x;
                oa[a][1] += s * vv.y;
                oa[a][2] += s * vv.z;
                oa[a][3] += s * vv.w;
            }
        }

#pragma unroll
        for (int a = 0; a < 4; a++) {
            int p = pg + 16 * a;
            if (p < 49) {
                int r = p / 7, c = p - r * 7;
                int hh = wi * 7 + r + shift; if (hh >= 56) hh -= 56;
                int ww = wj * 7 + c + shift; if (ww >= 56) ww -= 56;
                size_t tok = (size_t)bimg * 3136 + hh * 56 + ww;
                float4 res = make_float4(oa[a][0], oa[a][1], oa[a][2], oa[a][3]);
                *(float4*)&o[tok * 384 + head * 32 + d4] = res;
            }
        }
    }
}

// ---------------- launcher --------------------------------------------------
extern "C" void kernel_launch(void* const* d_in, const int* in_sizes, int n_in,
                              void* d_out, int out_size)
{
    const float* x     = (const float*)d_in[0];
    const float* n1g   = (const float*)d_in[1];
    const float* n1b   = (const float*)d_in[2];
    const float* qkvw  = (const float*)d_in[3];
    const float* qkvb  = (const float*)d_in[4];
    const float* rpb   = (const float*)d_in[5];
    const float* projw = (const float*)d_in[6];
    const float* projb = (const float*)d_in[7];
    const float* n2g   = (const float*)d_in[8];
    const float* n2b   = (const float*)d_in[9];
    const float* fc1w  = (const float*)d_in[10];
    const float* fc1b  = (const float*)d_in[11];
    const float* fc2w  = (const float*)d_in[12];
    const float* fc2b  = (const float*)d_in[13];
    float* out = (float*)d_out;

    float *p_xn, *p_qkv, *p_o, *p_h1;
    cudaGetSymbolAddress((void**)&p_xn,  g_xn);
    cudaGetSymbolAddress((void**)&p_qkv, g_qkv);
    cudaGetSymbolAddress((void**)&p_o,   g_o);
    cudaGetSymbolAddress((void**)&p_h1,  g_h1);

    cudaFuncSetAttribute(gemm_tf32<0>, cudaFuncAttributeMaxDynamicSharedMemorySize, GEMM_SMEM);
    cudaFuncSetAttribute(gemm_tf32<1>, cudaFuncAttributeMaxDynamicSharedMemorySize, GEMM_SMEM);
    cudaFuncSetAttribute(gemm_tf32<2>, cudaFuncAttributeMaxDynamicSharedMemorySize, GEMM_SMEM);

    int n4 = TOK * 384 / 4;
    copy_kernel<<<(n4 + 255) / 256, 256>>>((const float4*)x, (float4*)out, n4);

    for (int i = 0; i < 2; i++) {
        int shift = i ? 3 : 0;
        // LN1
        ln_kernel<<<TOK, 128>>>(out, n1g + i * 384, n1b + i * 384, p_xn);
        // QKV projection
        gemm_tf32<0><<<dim3(9, 392), 256, GEMM_SMEM>>>(p_xn, qkvw + (size_t)i * 384 * 1152,
                                                       qkvb + i * 1152, p_qkv, TOK, 1152, 384);
        // windowed attention
        attn_kernel<<<12288, 128>>>(p_qkv, rpb + i * 169 * 12, p_o, shift);
        // output projection + residual into stream
        gemm_tf32<2><<<dim3(3, 392), 256, GEMM_SMEM>>>(p_o, projw + (size_t)i * 384 * 384,
                                                       projb + i * 384, out, TOK, 384, 384);
        // LN2
        ln_kernel<<<TOK, 128>>>(out, n2g + i * 384, n2b + i * 384, p_xn);
        // MLP fc1 + GELU
        gemm_tf32<1><<<dim3(12, 392), 256, GEMM_SMEM>>>(p_xn, fc1w + (size_t)i * 384 * 1536,
                                                        fc1b + i * 1536, p_h1, TOK, 1536, 384);
        // MLP fc2 + residual
        gemm_tf32<2><<<dim3(3, 392), 256, GEMM_SMEM>>>(p_h1, fc2w + (size_t)i * 1536 * 384,
                                                       fc2b + i * 384, out, TOK, 384, 1536);
    }
}

// round 5
// speedup vs baseline: 1.3329x; 1.1576x over previous
#include <cuda_runtime.h>
#include <cuda_fp16.h>
#include <cstdint>
#include <math.h>

#define TOK 50176            // 16 * 56 * 56 tokens

// ---------------- scratch (device globals; no allocation allowed) ----------
__device__ __half g_xn [TOK * 384];    // LN output (fp16)
__device__ __half g_qkv[TOK * 1152];   // QKV activations (fp16)
__device__ __half g_o  [TOK * 384];    // attention output (fp16)
__device__ __half g_h1 [TOK * 1536];   // MLP hidden (fp16)
__device__ __half g_wt [2 * 1769472];  // transposed fp16 weights [N,K] per block

// ---------------- helpers ----------------------------------------------------
__device__ __forceinline__ void cp16s(uint32_t saddr, const void* g)
{
    asm volatile("cp.async.cg.shared.global [%0], [%1], 16;\n" :: "r"(saddr), "l"(g));
}
__device__ __forceinline__ uint32_t smem_u32(const void* p)
{
    uint32_t a;
    asm("{ .reg .u64 t; cvta.to.shared.u64 t, %1; cvt.u32.u64 %0, t; }" : "=r"(a) : "l"(p));
    return a;
}
#define LDSM4(r0, r1, r2, r3, addr) \
    asm volatile("ldmatrix.sync.aligned.m8n8.x4.shared.b16 {%0,%1,%2,%3}, [%4];" \
                 : "=r"(r0), "=r"(r1), "=r"(r2), "=r"(r3) : "r"(addr))

// ---------------- fp16 tensor-core GEMM, 2-stage cp.async ------------------
// C[M,N] = A[M,K] @ Bt[N,K]^T + bias   (A,Bt fp16; accumulate fp32)
// MODE 0: store fp16   MODE 1: gelu -> fp16   MODE 2: fp32 residual add
#define BK 64
#define PITCH 72                       // halves per smem row (144B, conflict-free)
#define STG_A (128 * PITCH * 2)        // 18432 B per A stage
#define SM_A0 0
#define SM_A1 STG_A
#define SM_B0 (2 * STG_A)
#define SM_B1 (3 * STG_A)
#define SM_BIAS (4 * STG_A)
#define GEMM_SMEM (4 * STG_A + 512)

template<int MODE, typename TOut>
__global__ __launch_bounds__(256, 1)
void gemm_fp16(const __half* __restrict__ A, const __half* __restrict__ Bt,
               const float* __restrict__ bias, TOut* __restrict__ Cout,
               int N, int K)
{
    extern __shared__ __align__(1024) char smem[];
    uint32_t sb = smem_u32(smem);
    float* bias_s = (float*)(smem + SM_BIAS);

    int tid  = threadIdx.x;
    int bn   = blockIdx.x, bm = blockIdx.y;
    int warp = tid >> 5, lane = tid & 31;
    int wm   = warp & 3;            // 4 warps along M (32 rows)
    int wn   = warp >> 2;           // 2 warps along N (64 cols)
    int g    = lane >> 2, t = lane & 3;
    int sub  = lane >> 3, r = lane & 7;

    if (tid < 128) bias_s[tid] = bias[bn * 128 + tid];

    float acc[2][8][4];
#pragma unroll
    for (int i = 0; i < 2; i++)
#pragma unroll
        for (int j = 0; j < 8; j++)
#pragma unroll
            for (int k = 0; k < 4; k++) acc[i][j][k] = 0.f;

    const __half* Ag = A  + (size_t)bm * 128 * K;
    const __half* Bg = Bt + (size_t)bn * 128 * K;

    // cp.async indices: 1024 x 16B per tile, 4 per thread
    int ldrow = tid >> 1;                    // 0..127
    int ldc0  = (tid & 1) * 4;               // chunk base 0 or 4 (each chunk 8 halves)

    // ldmatrix lane byte-offsets (relative to stage base)
    uint32_t aoff = (uint32_t)(((wm * 32 + (lane & 15)) * PITCH + (lane >> 4) * 8) * 2);
    uint32_t boff = (uint32_t)(((wn * 64 + (sub >> 1) * 8 + r) * PITCH + (sub & 1) * 8) * 2);

    // prologue: chunk 0 -> stage 0
#pragma unroll
    for (int c = 0; c < 4; c++) {
        cp16s(sb + SM_A0 + (uint32_t)(ldrow * PITCH + (ldc0 + c) * 8) * 2,
              Ag + (size_t)ldrow * K + (ldc0 + c) * 8);
        cp16s(sb + SM_B0 + (uint32_t)(ldrow * PITCH + (ldc0 + c) * 8) * 2,
              Bg + (size_t)ldrow * K + (ldc0 + c) * 8);
    }
    asm volatile("cp.async.commit_group;");

    int NK = K / BK;
    for (int kc = 0; kc < NK; kc++) {
        int p = kc & 1;
        if (kc + 1 < NK) {
            uint32_t sa = sb + (p ? SM_A0 : SM_A1);
            uint32_t sbf = sb + (p ? SM_B0 : SM_B1);
            int k0 = (kc + 1) * BK;
#pragma unroll
            for (int c = 0; c < 4; c++) {
                cp16s(sa  + (uint32_t)(ldrow * PITCH + (ldc0 + c) * 8) * 2,
                      Ag + (size_t)ldrow * K + k0 + (ldc0 + c) * 8);
                cp16s(sbf + (uint32_t)(ldrow * PITCH + (ldc0 + c) * 8) * 2,
                      Bg + (size_t)ldrow * K + k0 + (ldc0 + c) * 8);
            }
            asm volatile("cp.async.commit_group;");
            asm volatile("cp.async.wait_group 1;");
        } else {
            asm volatile("cp.async.wait_group 0;");
        }
        __syncthreads();

        uint32_t abase = sb + (p ? SM_A1 : SM_A0) + aoff;
        uint32_t bbase = sb + (p ? SM_B1 : SM_B0) + boff;
#pragma unroll
        for (int ks = 0; ks < 4; ks++) {
            uint32_t a[2][4];
#pragma unroll
            for (int mt = 0; mt < 2; mt++)
                LDSM4(a[mt][0], a[mt][1], a[mt][2], a[mt][3],
                      abase + mt * (16 * PITCH * 2) + ks * 32);
            uint32_t b[4][4];
#pragma unroll
            for (int np = 0; np < 4; np++)
                LDSM4(b[np][0], b[np][1], b[np][2], b[np][3],
                      bbase + np * (16 * PITCH * 2) + ks * 32);
#pragma unroll
            for (int mt = 0; mt < 2; mt++)
#pragma unroll
                for (int nt = 0; nt < 8; nt++) {
                    uint32_t b0 = b[nt >> 1][(nt & 1) * 2];
                    uint32_t b1 = b[nt >> 1][(nt & 1) * 2 + 1];
                    asm volatile(
                        "mma.sync.aligned.m16n8k16.row.col.f32.f16.f16.f32 "
                        "{%0,%1,%2,%3}, {%4,%5,%6,%7}, {%8,%9}, {%0,%1,%2,%3};\n"
                        : "+f"(acc[mt][nt][0]), "+f"(acc[mt][nt][1]),
                          "+f"(acc[mt][nt][2]), "+f"(acc[mt][nt][3])
                        : "r"(a[mt][0]), "r"(a[mt][1]), "r"(a[mt][2]), "r"(a[mt][3]),
                          "r"(b0), "r"(b1));
                }
        }
        __syncthreads();
    }

    // epilogue
#pragma unroll
    for (int mt = 0; mt < 2; mt++) {
#pragma unroll
        for (int nt = 0; nt < 8; nt++) {
            int row = bm * 128 + wm * 32 + mt * 16 + g;
            int col = bn * 128 + wn * 64 + nt * 8 + t * 2;
            int cl  = wn * 64 + nt * 8 + t * 2;
            float b0 = bias_s[cl], b1 = bias_s[cl + 1];
            float v00 = acc[mt][nt][0] + b0, v01 = acc[mt][nt][1] + b1;
            float v10 = acc[mt][nt][2] + b0, v11 = acc[mt][nt][3] + b1;
            if (MODE == 1) {
                v00 = 0.5f * v00 * (1.f + erff(v00 * 0.70710678118654752f));
                v01 = 0.5f * v01 * (1.f + erff(v01 * 0.70710678118654752f));
                v10 = 0.5f * v10 * (1.f + erff(v10 * 0.70710678118654752f));
                v11 = 0.5f * v11 * (1.f + erff(v11 * 0.70710678118654752f));
            }
            size_t i0 = (size_t)row * N + col;
            size_t i1 = (size_t)(row + 8) * N + col;
            if (MODE == 2) {
                float* C = (float*)Cout;
                C[i0] += v00; C[i0 + 1] += v01;
                C[i1] += v10; C[i1 + 1] += v11;
            } else {
                __half* C = (__half*)Cout;
                __half2 h0 = __floats2half2_rn(v00, v01);
                __half2 h1 = __floats2half2_rn(v10, v11);
                *(__half2*)(C + i0) = h0;
                *(__half2*)(C + i1) = h1;
            }
        }
    }
}

// ---------------- weight transpose+convert [K,N] f32 -> [N,K] f16 ----------
__global__ void transpose_kernel(const float* __restrict__ s, __half* __restrict__ d,
                                 int K, int N)
{
    __shared__ float t[32][33];
    int bx = blockIdx.x * 32, by = blockIdx.y * 32;
    int x = threadIdx.x, y = threadIdx.y;
#pragma unroll
    for (int yy = y; yy < 32; yy += 8)
        t[yy][x] = s[(size_t)(by + yy) * N + bx + x];
    __syncthreads();
#pragma unroll
    for (int yy = y; yy < 32; yy += 8)
        d[(size_t)(bx + yy) * K + by + x] = __float2half(t[x][yy]);
}

// ---------------- copy input -> residual stream (d_out) --------------------
__global__ void copy_kernel(const float4* __restrict__ src, float4* __restrict__ dst, int n4)
{
    int i = blockIdx.x * blockDim.x + threadIdx.x;
    if (i < n4) dst[i] = src[i];
}

// ---------------- LayerNorm (C=384): fp32 in, fp16 out ---------------------
__global__ __launch_bounds__(128)
void ln_kernel(const float* __restrict__ x, const float* __restrict__ gw,
               const float* __restrict__ bw, __half* __restrict__ out)
{
    __shared__ float rs[4], rq[4];
    int t = threadIdx.x;
    size_t base = (size_t)blockIdx.x * 384;
    float v0 = x[base + t], v1 = x[base + t + 128], v2 = x[base + t + 256];
    float s = v0 + v1 + v2;
    float q = v0*v0 + v1*v1 + v2*v2;
#pragma unroll
    for (int o = 16; o > 0; o >>= 1) {
        s += __shfl_xor_sync(0xffffffffu, s, o);
        q += __shfl_xor_sync(0xffffffffu, q, o);
    }
    if ((t & 31) == 0) { rs[t >> 5] = s; rq[t >> 5] = q; }
    __syncthreads();
    float mean = (rs[0] + rs[1] + rs[2] + rs[3]) * (1.0f / 384.0f);
    float var  = (rq[0] + rq[1] + rq[2] + rq[3]) * (1.0f / 384.0f) - mean * mean;
    float inv  = rsqrtf(var + 1e-5f);
    out[base + t]       = __float2half((v0 - mean) * inv * gw[t]       + bw[t]);
    out[base + t + 128] = __float2half((v1 - mean) * inv * gw[t + 128] + bw[t + 128]);
    out[base + t + 256] = __float2half((v2 - mean) * inv * gw[t + 256] + bw[t + 256]);
}

// ---------------- windowed attention: one block per (window, head) ---------
__global__ __launch_bounds__(128)
void attn_kernel(const __half* __restrict__ qkv, const float* __restrict__ rpb,
                 __half* __restrict__ o, int shift)
{
    __shared__ float qs[56][33];
    __shared__ float ks[64][33];
    __shared__ float vs[49][36];
    __shared__ float sm[49 * 49];
    __shared__ float rps[169];

    int head = blockIdx.x % 12;
    int win  = blockIdx.x / 12;
    int bimg = win >> 6;
    int wi   = (win >> 3) & 7;
    int wj   = win & 7;
    int tid  = threadIdx.x;

    for (int idx = tid; idx < 169; idx += 128) rps[idx] = rpb[idx * 12 + head];

    for (int idx = tid; idx < 49 * 32; idx += 128) {
        int p = idx >> 5, d = idx & 31;
        int r = p / 7, c = p - r * 7;
        int hh = wi * 7 + r + shift; if (hh >= 56) hh -= 56;
        int ww = wj * 7 + c + shift; if (ww >= 56) ww -= 56;
        size_t tok = (size_t)bimg * 3136 + hh * 56 + ww;
        const __half* bp = qkv + tok * 1152 + head * 32 + d;
        qs[p][d] = __half2float(bp[0]) * 0.17677669529663687f;
        ks[p][d] = __half2float(bp[384]);
        vs[p][d] = __half2float(bp[768]);
    }
    __syncthreads();

    {
        int p0 = tid >> 4;
        int j0 = tid & 15;
        float acc[7][4];
#pragma unroll
        for (int a = 0; a < 7; a++)
#pragma unroll
            for (int b = 0; b < 4; b++) acc[a][b] = 0.f;

#pragma unroll 4
        for (int d = 0; d < 32; d++) {
            float kv[4];
#pragma unroll
            for (int b = 0; b < 4; b++) kv[b] = ks[j0 + 16 * b][d];
#pragma unroll
            for (int a = 0; a < 7; a++) {
                float qv = qs[p0 + 8 * a][d];
#pragma unroll
                for (int b = 0; b < 4; b++) acc[a][b] += qv * kv[b];
            }
        }

#pragma unroll
        for (int a = 0; a < 7; a++) {
            int p = p0 + 8 * a;
            if (p < 49) {
                int rp = p / 7, cp = p - rp * 7;
                int regp = 0;
                if (shift > 0) {
                    int hp = wi * 7 + rp, wp_ = wj * 7 + cp;
                    regp = (hp < 49 ? 0 : (hp < 53 ? 1 : 2)) * 3 +
                           (wp_ < 49 ? 0 : (wp_ < 53 ? 1 : 2));
                }
#pragma unroll
                for (int b = 0; b < 4; b++) {
                    int j = j0 + 16 * b;
                    if (j < 49) {
                        int rj = j / 7, cj = j - rj * 7;
                        float s = acc[a][b] + rps[(rp - rj + 6) * 13 + (cp - cj + 6)];
                        if (shift > 0) {
                            int hj = wi * 7 + rj, wq = wj * 7 + cj;
                            int regj = (hj < 49 ? 0 : (hj < 53 ? 1 : 2)) * 3 +
                                       (wq < 49 ? 0 : (wq < 53 ? 1 : 2));
                            if (regp != regj) s -= 100.f;
                        }
                        sm[p * 49 + j] = s;
                    }
                }
            }
        }
    }
    __syncthreads();

    {
        int wd = tid >> 5, lane = tid & 31;
        for (int r = wd; r < 49; r += 4) {
            float v0 = sm[r * 49 + lane];
            float v1 = (lane + 32 < 49) ? sm[r * 49 + lane + 32] : -1e30f;
            float mx = fmaxf(v0, v1);
#pragma unroll
            for (int off = 16; off > 0; off >>= 1)
                mx = fmaxf(mx, __shfl_xor_sync(0xffffffffu, mx, off));
            float e0 = __expf(v0 - mx);
            float e1 = (lane + 32 < 49) ? __expf(v1 - mx) : 0.f;
            float sum = e0 + e1;
#pragma unroll
            for (int off = 16; off > 0; off >>= 1)
                sum += __shfl_xor_sync(0xffffffffu, sum, off);
            float inv = 1.f / sum;
            sm[r * 49 + lane] = e0 * inv;
            if (lane + 32 < 49) sm[r * 49 + lane + 32] = e1 * inv;
        }
    }
    __syncthreads();

    {
        int pg = tid >> 3;
        int d4 = (tid & 7) * 4;
        float oa[4][4];
#pragma unroll
        for (int a = 0; a < 4; a++)
#pragma unroll
            for (int k = 0; k < 4; k++) oa[a][k] = 0.f;

        for (int j = 0; j < 49; j++) {
            float4 vv = *(const float4*)&vs[j][d4];
#pragma unroll
            for (int a = 0; a < 4; a++) {
                int p = pg + 16 * a;
                int pr = p < 49 ? p : 0;
                float s = sm[pr * 49 + j];
                oa[a][0] += s * vv.x;
                oa[a][1] += s * vv.y;
                oa[a][2] += s * vv.z;
                oa[a][3] += s * vv.w;
            }
        }

#pragma unroll
        for (int a = 0; a < 4; a++) {
            int p = pg + 16 * a;
            if (p < 49) {
                int r = p / 7, c = p - r * 7;
                int hh = wi * 7 + r + shift; if (hh >= 56) hh -= 56;
                int ww = wj * 7 + c + shift; if (ww >= 56) ww -= 56;
                size_t tok = (size_t)bimg * 3136 + hh * 56 + ww;
                __half2 h0 = __floats2half2_rn(oa[a][0], oa[a][1]);
                __half2 h1 = __floats2half2_rn(oa[a][2], oa[a][3]);
                __half2* dst = (__half2*)&o[tok * 384 + head * 32 + d4];
                dst[0] = h0;
                dst[1] = h1;
            }
        }
    }
}

// ---------------- launcher --------------------------------------------------
extern "C" void kernel_launch(void* const* d_in, const int* in_sizes, int n_in,
                              void* d_out, int out_size)
{
    const float* x     = (const float*)d_in[0];
    const float* n1g   = (const float*)d_in[1];
    const float* n1b   = (const float*)d_in[2];
    const float* qkvw  = (const float*)d_in[3];
    const float* qkvb  = (const float*)d_in[4];
    const float* rpb   = (const float*)d_in[5];
    const float* projw = (const float*)d_in[6];
    const float* projb = (const float*)d_in[7];
    const float* n2g   = (const float*)d_in[8];
    const float* n2b   = (const float*)d_in[9];
    const float* fc1w  = (const float*)d_in[10];
    const float* fc1b  = (const float*)d_in[11];
    const float* fc2w  = (const float*)d_in[12];
    const float* fc2b  = (const float*)d_in[13];
    float* out = (float*)d_out;

    __half *p_xn, *p_qkv, *p_o, *p_h1, *p_wt;
    cudaGetSymbolAddress((void**)&p_xn,  g_xn);
    cudaGetSymbolAddress((void**)&p_qkv, g_qkv);
    cudaGetSymbolAddress((void**)&p_o,   g_o);
    cudaGetSymbolAddress((void**)&p_h1,  g_h1);
    cudaGetSymbolAddress((void**)&p_wt,  g_wt);

    cudaFuncSetAttribute((void*)gemm_fp16<0, __half>, cudaFuncAttributeMaxDynamicSharedMemorySize, GEMM_SMEM);
    cudaFuncSetAttribute((void*)gemm_fp16<1, __half>, cudaFuncAttributeMaxDynamicSharedMemorySize, GEMM_SMEM);
    cudaFuncSetAttribute((void*)gemm_fp16<2, float>,  cudaFuncAttributeMaxDynamicSharedMemorySize, GEMM_SMEM);

    // transpose+convert all weights to [N,K] fp16 once per call
    for (int i = 0; i < 2; i++) {
        size_t base = (size_t)i * 1769472;
        transpose_kernel<<<dim3(1152/32, 384/32), dim3(32, 8)>>>(
            qkvw + (size_t)i * 384 * 1152, p_wt + base, 384, 1152);
        transpose_kernel<<<dim3(384/32, 384/32), dim3(32, 8)>>>(
            projw + (size_t)i * 384 * 384, p_wt + base + 442368, 384, 384);
        transpose_kernel<<<dim3(1536/32, 384/32), dim3(32, 8)>>>(
            fc1w + (size_t)i * 384 * 1536, p_wt + base + 589824, 384, 1536);
        transpose_kernel<<<dim3(384/32, 1536/32), dim3(32, 8)>>>(
            fc2w + (size_t)i * 1536 * 384, p_wt + base + 1179648, 1536, 384);
    }

    int n4 = TOK * 384 / 4;
    copy_kernel<<<(n4 + 255) / 256, 256>>>((const float4*)x, (float4*)out, n4);

    for (int i = 0; i < 2; i++) {
        int shift = i ? 3 : 0;
        size_t base = (size_t)i * 1769472;
        // LN1
        ln_kernel<<<TOK, 128>>>(out, n1g + i * 384, n1b + i * 384, p_xn);
        // QKV projection
        gemm_fp16<0, __half><<<dim3(9, 392), 256, GEMM_SMEM>>>(
            p_xn, p_wt + base, qkvb + i * 1152, p_qkv, 1152, 384);
        // windowed attention
        attn_kernel<<<12288, 128>>>(p_qkv, rpb + i * 169 * 12, p_o, shift);
        // output projection + residual
        gemm_fp16<2, float><<<dim3(3, 392), 256, GEMM_SMEM>>>(
            p_o, p_wt + base + 442368, projb + i * 384, out, 384, 384);
        // LN2
        ln_kernel<<<TOK, 128>>>(out, n2g + i * 384, n2b + i * 384, p_xn);
        // MLP fc1 + GELU
        gemm_fp16<1, __half><<<dim3(12, 392), 256, GEMM_SMEM>>>(
            p_xn, p_wt + base + 589824, fc1b + i * 1536, p_h1, 1536, 384);
        // MLP fc2 + residual
        gemm_fp16<2, float><<<dim3(3, 392), 256, GEMM_SMEM>>>(
            p_h1, p_wt + base + 1179648, fc2b + i * 384, out, 384, 1536);
    }
}